// round 6
// baseline (speedup 1.0000x reference)
#include <cuda_runtime.h>
#include <cuda_fp16.h>
#include <cstdint>

#define IN_DIM  128
#define OUT_DIM 128
#define NHEADS  4
#define NEG_SLOPE 0.2f

#define N_MAX 50000
#define E_MAX 1600000
#define FULL 0xFFFFFFFFu
#define MAXC 4   // cached score strips: covers deg <= 128

// -------- device scratch (static: no allocation allowed) --------
__device__ float  g_hq   [N_MAX * NHEADS];
__device__ float  g_kact [N_MAX * NHEADS];
__device__ float  g_qagg [N_MAX * NHEADS];
__device__ __half g_hproj[(size_t)N_MAX * OUT_DIM];
__device__ float  g_alpha[E_MAX];
__device__ int    g_cnt  [N_MAX];   // zero-initialized at load; re-zeroed by scan_kernel
__device__ int    g_off  [N_MAX + 1];
__device__ int    g_pos  [N_MAX];
__device__ int    g_csr_col[E_MAX];

// -------- streams/events for graph-DAG fork/join (created pre-main) --------
struct StreamInit {
    cudaStream_t s1;
    cudaEvent_t ev_fork, ev_proj;
    StreamInit() {
        cudaStreamCreateWithFlags(&s1, cudaStreamNonBlocking);
        cudaEventCreateWithFlags(&ev_fork, cudaEventDisableTiming);
        cudaEventCreateWithFlags(&ev_proj, cudaEventDisableTiming);
    }
};
static StreamInit g_si;

// ================= kernel: projections (runs on side stream) =========
#define NPB 16
__global__ __launch_bounds__(128) void proj_kernel(
    const float* __restrict__ x,
    const float* __restrict__ Wq, const float* __restrict__ Wk,
    const float* __restrict__ Wl, const float* __restrict__ bl, int N)
{
    __shared__ float xs[NPB * IN_DIM];
    const int t = threadIdx.x;
    const int base = blockIdx.x * NPB;
    const int nn = min(NPB, N - base);
    if (nn <= 0) return;

    {
        const float4* xg = (const float4*)(x + (size_t)base * IN_DIM);
        float4* xs4 = (float4*)xs;
        const int tot4 = nn * (IN_DIM / 4);
        for (int i = t; i < tot4; i += 128) xs4[i] = xg[i];
    }
    __syncthreads();

    // per-head q/k projections: t = n2*8 + h
    {
        const int n2 = t >> 3;
        const int h  = t & 7;
        if (n2 < nn) {
            const float* wrow = (h < 4) ? (Wq + h * IN_DIM) : (Wk + (h - 4) * IN_DIM);
            const float4* w4 = (const float4*)wrow;
            const float4* xr = (const float4*)(xs + n2 * IN_DIM);
            float d = 0.0f;
            #pragma unroll
            for (int k = 0; k < IN_DIM / 4; k++) {
                float4 w = w4[k]; float4 xv = xr[k];
                d += w.x * xv.x + w.y * xv.y + w.z * xv.z + w.w * xv.w;
            }
            const int node = base + n2;
            if (h < 4) g_hq[node * NHEADS + h] = d;
            else       g_kact[node * NHEADS + (h - 4)] = (d >= 0.0f) ? d : NEG_SLOPE * d;
        }
    }

    float acc[NPB];
    #pragma unroll
    for (int n = 0; n < NPB; n++) acc[n] = 0.0f;

    const float4* wl4 = (const float4*)(Wl + (size_t)t * IN_DIM);
    #pragma unroll 4
    for (int k = 0; k < IN_DIM / 4; k++) {
        float4 w = wl4[k];
        #pragma unroll
        for (int n = 0; n < NPB; n++) {
            float4 xv = ((const float4*)(xs + n * IN_DIM))[k];
            acc[n] += w.x * xv.x + w.y * xv.y + w.z * xv.z + w.w * xv.w;
        }
    }
    const float b = bl[t];
    for (int n = 0; n < nn; n++)
        g_hproj[(size_t)(base + n) * OUT_DIM + t] = __float2half_rn(acc[n] + b);
}

// ================= kernel: histogram of rows =================
__global__ __launch_bounds__(256) void hist_kernel(const int* __restrict__ rows, int E) {
    int e = blockIdx.x * 256 + threadIdx.x;
    if (e < E) atomicAdd(&g_cnt[rows[e]], 1);
}

// ================= single-block scan (also re-zeros g_cnt) ============
__device__ __forceinline__ int warp_incl_scan(int v, int lane) {
    #pragma unroll
    for (int d = 1; d < 32; d <<= 1) {
        int t = __shfl_up_sync(FULL, v, d);
        if (lane >= d) v += t;
    }
    return v;
}

__global__ __launch_bounds__(1024) void scan_kernel(int N, int E) {
    const int tid = threadIdx.x;
    const int lane = tid & 31, wid = tid >> 5;
    __shared__ int wtot[32];
    int carry = 0;
    for (int base = 0; base < N; base += 1024) {
        int i = base + tid;
        int v = 0;
        if (i < N) { v = g_cnt[i]; g_cnt[i] = 0; }
        int s = warp_incl_scan(v, lane);
        if (lane == 31) wtot[wid] = s;
        __syncthreads();
        if (wid == 0) {
            int ws = wtot[lane];
            #pragma unroll
            for (int d = 1; d < 32; d <<= 1) {
                int t = __shfl_up_sync(FULL, ws, d);
                if (lane >= d) ws += t;
            }
            wtot[lane] = ws;
        }
        __syncthreads();
        int excl = carry + (wid ? wtot[wid - 1] : 0) + s - v;
        if (i < N) { g_off[i] = excl; g_pos[i] = excl; }
        int tot = wtot[31];
        __syncthreads();
        carry += tot;
    }
    if (tid == 0) g_off[N] = E;
}

// ================= kernel: scatter edges into CSR =================
__global__ __launch_bounds__(256) void scatter_kernel(
    const int* __restrict__ rows, const int* __restrict__ cols, int E)
{
    int e = blockIdx.x * 256 + threadIdx.x;
    if (e >= E) return;
    int r = rows[e];
    int p = atomicAdd(&g_pos[r], 1);
    g_csr_col[p] = cols[e];
}

// ================= kernel: q_agg via CSR (no atomics) =================
__global__ __launch_bounds__(256) void qagg_csr_kernel(int N) {
    int w = (blockIdx.x * 256 + threadIdx.x) >> 5;
    int lane = threadIdx.x & 31;
    if (w >= N) return;
    int beg = g_off[w], end = g_off[w + 1];
    float4 acc = {0.f, 0.f, 0.f, 0.f};
    for (int e = beg + lane; e < end; e += 32) {
        int c = __ldg(g_csr_col + e);
        float4 v = __ldg(((const float4*)g_hq) + c);
        acc.x += v.x; acc.y += v.y; acc.z += v.z; acc.w += v.w;
    }
    #pragma unroll
    for (int d = 16; d; d >>= 1) {
        acc.x += __shfl_xor_sync(FULL, acc.x, d);
        acc.y += __shfl_xor_sync(FULL, acc.y, d);
        acc.z += __shfl_xor_sync(FULL, acc.z, d);
        acc.w += __shfl_xor_sync(FULL, acc.w, d);
    }
    if (lane == 0) ((float4*)g_qagg)[w] = acc;
}

// ================= softmax + per-edge alpha (warp per node) ==========
__global__ __launch_bounds__(256) void softmax_alpha_kernel(int N) {
    int node = (blockIdx.x * 256 + threadIdx.x) >> 5;
    int lane = threadIdx.x & 31;
    if (node >= N) return;
    const int beg = g_off[node], end = g_off[node + 1];
    const int deg = end - beg;
    if (deg == 0) return;

    const float4 ka = ((const float4*)g_kact)[node];
    const int nstr = (deg + 31) >> 5;

    if (nstr <= MAXC) {
        // ---- fast path: cache scores in registers (ONE q-gather pass)
        float4 sc[MAXC];
        float4 mx = {-3.4e38f, -3.4e38f, -3.4e38f, -3.4e38f};
        #pragma unroll
        for (int s = 0; s < MAXC; s++) {
            sc[s] = make_float4(0.f, 0.f, 0.f, 0.f);
            if (s < nstr) {
                int e = beg + s * 32 + lane;
                if (e < end) {
                    int c = __ldg(g_csr_col + e);
                    float4 q = __ldg(((const float4*)g_qagg) + c);
                    sc[s].x = ka.x * q.x; sc[s].y = ka.y * q.y;
                    sc[s].z = ka.z * q.z; sc[s].w = ka.w * q.w;
                    mx.x = fmaxf(mx.x, sc[s].x); mx.y = fmaxf(mx.y, sc[s].y);
                    mx.z = fmaxf(mx.z, sc[s].z); mx.w = fmaxf(mx.w, sc[s].w);
                }
            }
        }
        #pragma unroll
        for (int d = 16; d; d >>= 1) {
            mx.x = fmaxf(mx.x, __shfl_xor_sync(FULL, mx.x, d));
            mx.y = fmaxf(mx.y, __shfl_xor_sync(FULL, mx.y, d));
            mx.z = fmaxf(mx.z, __shfl_xor_sync(FULL, mx.z, d));
            mx.w = fmaxf(mx.w, __shfl_xor_sync(FULL, mx.w, d));
        }
        float4 sm = {0.f, 0.f, 0.f, 0.f};
        #pragma unroll
        for (int s = 0; s < MAXC; s++) {
            if (s < nstr) {
                int e = beg + s * 32 + lane;
                if (e < end) {
                    sc[s].x = __expf(sc[s].x - mx.x);
                    sc[s].y = __expf(sc[s].y - mx.y);
                    sc[s].z = __expf(sc[s].z - mx.z);
                    sc[s].w = __expf(sc[s].w - mx.w);
                    sm.x += sc[s].x; sm.y += sc[s].y; sm.z += sc[s].z; sm.w += sc[s].w;
                }
            }
        }
        #pragma unroll
        for (int d = 16; d; d >>= 1) {
            sm.x += __shfl_xor_sync(FULL, sm.x, d);
            sm.y += __shfl_xor_sync(FULL, sm.y, d);
            sm.z += __shfl_xor_sync(FULL, sm.z, d);
            sm.w += __shfl_xor_sync(FULL, sm.w, d);
        }
        float4 inv;
        inv.x = 0.25f * __fdividef(1.0f, sm.x + 1e-8f);
        inv.y = 0.25f * __fdividef(1.0f, sm.y + 1e-8f);
        inv.z = 0.25f * __fdividef(1.0f, sm.z + 1e-8f);
        inv.w = 0.25f * __fdividef(1.0f, sm.w + 1e-8f);
        #pragma unroll
        for (int s = 0; s < MAXC; s++) {
            if (s < nstr) {
                int e = beg + s * 32 + lane;
                if (e < end)
                    g_alpha[e] = sc[s].x * inv.x + sc[s].y * inv.y
                               + sc[s].z * inv.z + sc[s].w * inv.w;
            }
        }
    } else {
        // ---- fallback (deg > 128): two gather passes
        float4 mx = {-3.4e38f, -3.4e38f, -3.4e38f, -3.4e38f};
        for (int e = beg + lane; e < end; e += 32) {
            int c = __ldg(g_csr_col + e);
            float4 q = __ldg(((const float4*)g_qagg) + c);
            mx.x = fmaxf(mx.x, ka.x * q.x);
            mx.y = fmaxf(mx.y, ka.y * q.y);
            mx.z = fmaxf(mx.z, ka.z * q.z);
            mx.w = fmaxf(mx.w, ka.w * q.w);
        }
        #pragma unroll
        for (int d = 16; d; d >>= 1) {
            mx.x = fmaxf(mx.x, __shfl_xor_sync(FULL, mx.x, d));
            mx.y = fmaxf(mx.y, __shfl_xor_sync(FULL, mx.y, d));
            mx.z = fmaxf(mx.z, __shfl_xor_sync(FULL, mx.z, d));
            mx.w = fmaxf(mx.w, __shfl_xor_sync(FULL, mx.w, d));
        }
        float4 sm = {0.f, 0.f, 0.f, 0.f};
        for (int e = beg + lane; e < end; e += 32) {
            int c = __ldg(g_csr_col + e);
            float4 q = __ldg(((const float4*)g_qagg) + c);
            sm.x += __expf(ka.x * q.x - mx.x);
            sm.y += __expf(ka.y * q.y - mx.y);
            sm.z += __expf(ka.z * q.z - mx.z);
            sm.w += __expf(ka.w * q.w - mx.w);
        }
        #pragma unroll
        for (int d = 16; d; d >>= 1) {
            sm.x += __shfl_xor_sync(FULL, sm.x, d);
            sm.y += __shfl_xor_sync(FULL, sm.y, d);
            sm.z += __shfl_xor_sync(FULL, sm.z, d);
            sm.w += __shfl_xor_sync(FULL, sm.w, d);
        }
        float4 inv;
        inv.x = 0.25f * __fdividef(1.0f, sm.x + 1e-8f);
        inv.y = 0.25f * __fdividef(1.0f, sm.y + 1e-8f);
        inv.z = 0.25f * __fdividef(1.0f, sm.z + 1e-8f);
        inv.w = 0.25f * __fdividef(1.0f, sm.w + 1e-8f);
        for (int e = beg + lane; e < end; e += 32) {
            int c = __ldg(g_csr_col + e);
            float4 q = __ldg(((const float4*)g_qagg) + c);
            g_alpha[e] = __expf(ka.x * q.x - mx.x) * inv.x
                       + __expf(ka.y * q.y - mx.y) * inv.y
                       + __expf(ka.z * q.z - mx.z) * inv.z
                       + __expf(ka.w * q.w - mx.w) * inv.w;
        }
    }
}

// ========== aggregation: warp per (node, 64-dim half), fp16 gathers ====
__global__ __launch_bounds__(256) void agg_kernel(float* __restrict__ out, int N) {
    int w = (blockIdx.x * 256 + threadIdx.x) >> 5;
    int lane = threadIdx.x & 31;
    int node = w >> 1;
    int half = w & 1;
    if (node >= N) return;
    const int beg = g_off[node], end = g_off[node + 1];

    float2* outp = ((float2*)out) + (size_t)node * 64 + half * 32 + lane;
    if (beg == end) { *outp = make_float2(0.f, 0.f); return; }

    const __half2* hp = ((const __half2*)g_hproj) + half * 32 + lane;
    float2 acc = {0.f, 0.f};
    for (int base = beg; base < end; base += 32) {
        int e = base + lane;
        float a = 0.0f; int c = 0;
        if (e < end) {
            a = __ldg(g_alpha + e);
            c = __ldg(g_csr_col + e);
        }
        int cnt = min(32, end - base);
        #pragma unroll 8
        for (int j = 0; j < 32; j++) {
            if (j >= cnt) break;
            float aj = __shfl_sync(FULL, a, j);
            int   cj = __shfl_sync(FULL, c, j);
            float2 v = __half22float2(__ldg(hp + (size_t)cj * 64));
            acc.x = fmaf(aj, v.x, acc.x);
            acc.y = fmaf(aj, v.y, acc.y);
        }
    }
    acc.x = (acc.x >= 0.f) ? acc.x : NEG_SLOPE * acc.x;
    acc.y = (acc.y >= 0.f) ? acc.y : NEG_SLOPE * acc.y;
    *outp = acc;
}

// ================= launch =================
extern "C" void kernel_launch(void* const* d_in, const int* in_sizes, int n_in,
                              void* d_out, int out_size)
{
    const float* x  = (const float*)d_in[0];
    const int*   ei = (const int*)d_in[1];
    const float* Wq = (const float*)d_in[2];
    const float* Wk = (const float*)d_in[3];
    const float* Wl = (const float*)d_in[4];
    const float* bl = (const float*)d_in[5];
    float* out = (float*)d_out;

    const int N = in_sizes[0] / IN_DIM;
    const int E = in_sizes[1] / 2;
    const int* rows = ei;
    const int* cols = ei + E;

    // ---- fork: proj runs on side stream, concurrent with CSR build ----
    cudaEventRecord(g_si.ev_fork, 0);
    cudaStreamWaitEvent(g_si.s1, g_si.ev_fork, 0);
    proj_kernel<<<(N + NPB - 1) / NPB, 128, 0, g_si.s1>>>(x, Wq, Wk, Wl, bl, N);
    cudaEventRecord(g_si.ev_proj, g_si.s1);

    // ---- main stream: CSR build + softmax chain ----
    hist_kernel<<<(E + 255) / 256, 256>>>(rows, E);
    scan_kernel<<<1, 1024>>>(N, E);
    scatter_kernel<<<(E + 255) / 256, 256>>>(rows, cols, E);
    qagg_csr_kernel<<<(N * 32 + 255) / 256, 256>>>(N);
    softmax_alpha_kernel<<<(N * 32 + 255) / 256, 256>>>(N);

    // ---- join: agg needs hproj (side stream) + alpha (main stream) ----
    cudaStreamWaitEvent(0, g_si.ev_proj, 0);
    agg_kernel<<<(2 * N * 32 + 255) / 256, 256>>>(out, N);
}